// round 9
// baseline (speedup 1.0000x reference)
#include <cuda_runtime.h>

// ---------------- problem constants ----------------
#define SB    2304          // S = H*W
#define BSR   4608          // B*S
#define DD    64
#define NHH   8
#define FFD   2048
#define NLAYER 8
#define KS    21
#define KK2   441
#define HH    48
#define WWD   48
#define CC    3
#define BB    2
#define EPSV  1e-5f
#define ZSPL  8

typedef unsigned long long u64;

// ---------------- scratch ----------------
__device__ float g_y[BSR * DD];
__device__ float g_qkv[BSR * 3 * DD];
__device__ float g_attno[BSR * DD];
__device__ float g_part[ZSPL * BSR * DD];
__device__ float g_ff[BSR * FFD];

// ---------------- packed f32x2 helpers ----------------
__device__ __forceinline__ u64 fma2(u64 a, u64 b, u64 c) {
    u64 d;
    asm("fma.rn.f32x2 %0, %1, %2, %3;" : "=l"(d) : "l"(a), "l"(b), "l"(c));
    return d;
}
__device__ __forceinline__ u64 mul2(u64 a, u64 b) {
    u64 d;
    asm("mul.rn.f32x2 %0, %1, %2;" : "=l"(d) : "l"(a), "l"(b));
    return d;
}
__device__ __forceinline__ u64 pack2(float lo, float hi) {
    u64 d;
    asm("mov.b64 %0, {%1, %2};" : "=l"(d) : "r"(__float_as_uint(lo)), "r"(__float_as_uint(hi)));
    return d;
}
__device__ __forceinline__ void unpack2(u64 v, float& lo, float& hi) {
    unsigned a, b;
    asm("mov.b64 {%0, %1}, %2;" : "=r"(a), "=r"(b) : "l"(v));
    lo = __uint_as_float(a); hi = __uint_as_float(b);
}
__device__ __forceinline__ float ex2f(float x) {
    float r;
    asm("ex2.approx.f32 %0, %1;" : "=f"(r) : "f"(x));
    return r;
}

// ---------------- conv 3x3 + BN + ReLU -> [B,S,D] ----------------
__global__ __launch_bounds__(256) void conv_bn_relu(
    const float* __restrict__ x, const float* __restrict__ w,
    const float* __restrict__ cb, const float* __restrict__ gma,
    const float* __restrict__ bta, const float* __restrict__ mean,
    const float* __restrict__ var, float* __restrict__ y)
{
    int idx = blockIdx.x * 256 + threadIdx.x;
    if (idx >= BSR * DD) return;
    int d = idx & 63;
    int s = (idx >> 6) % SB;
    int b = idx / (SB * DD);
    int hh = s / WWD, ww = s % WWD;
    float sum = cb[d];
    #pragma unroll
    for (int ci = 0; ci < 3; ci++) {
        #pragma unroll
        for (int kh = 0; kh < 3; kh++) {
            int ih = hh + kh - 1;
            if ((unsigned)ih >= HH) continue;
            #pragma unroll
            for (int kw = 0; kw < 3; kw++) {
                int iw = ww + kw - 1;
                if ((unsigned)iw >= WWD) continue;
                sum += x[((b * CC + ci) * HH + ih) * WWD + iw] *
                       w[((d * CC + ci) * 3 + kh) * 3 + kw];
            }
        }
    }
    sum = (sum - mean[d]) * rsqrtf(var[d] + EPSV) * gma[d] + bta[d];
    y[idx] = fmaxf(sum, 0.0f);
}

// ============================================================================
// gemm64d: C[M,N] = A[M,64] @ W[N,64]^T + bias.  128 threads, 64x64 tile.
// Thread = 16 rows x 2 cols. W pre-duplicated in smem as u64 -> no pack in loop.
// ============================================================================
template<int RELU>
__global__ __launch_bounds__(128) void gemm64d(
    const float* __restrict__ A, const float* __restrict__ W,
    const float* __restrict__ bias, float* __restrict__ C, int N)
{
    __shared__ float As[64][64];
    __shared__ u64  Wd[64][64];
    int tid = threadIdx.x;
    int rowBase = blockIdx.y * 64;
    int nBase = blockIdx.x * 64;

    // stage: thread covers row n = tid>>1, half = tid&1 (32 k-values)
    int sn = tid >> 1, half = tid & 1;
    {
        const float* ap = A + (rowBase + sn) * 64 + half * 32;
        #pragma unroll
        for (int j = 0; j < 8; j++) {
            float4 v = *(const float4*)(ap + j * 4);
            int k = half * 32 + j * 4;
            As[k][sn] = v.x; As[k+1][sn] = v.y; As[k+2][sn] = v.z; As[k+3][sn] = v.w;
        }
        int wn = nBase + sn;
        if (wn < N) {
            const float* wp = W + wn * 64 + half * 32;
            #pragma unroll
            for (int j = 0; j < 8; j++) {
                float4 v = *(const float4*)(wp + j * 4);
                int k = half * 32 + j * 4;
                Wd[k][sn]   = pack2(v.x, v.x);
                Wd[k+1][sn] = pack2(v.y, v.y);
                Wd[k+2][sn] = pack2(v.z, v.z);
                Wd[k+3][sn] = pack2(v.w, v.w);
            }
        } else {
            #pragma unroll
            for (int j = 0; j < 8; j++) {
                int k = half * 32 + j * 4;
                Wd[k][sn] = 0; Wd[k+1][sn] = 0; Wd[k+2][sn] = 0; Wd[k+3][sn] = 0;
            }
        }
    }
    __syncthreads();

    int tx = tid & 31, ty = tid >> 5;       // tx: col pair, ty: 16-row group
    u64 acc[8][2] = {};
    #pragma unroll 16
    for (int k = 0; k < 64; k++) {
        double2 a0 = *(const double2*)&As[k][ty * 16 + 0];
        double2 a1 = *(const double2*)&As[k][ty * 16 + 4];
        double2 a2 = *(const double2*)&As[k][ty * 16 + 8];
        double2 a3 = *(const double2*)&As[k][ty * 16 + 12];
        double2 wv = *(const double2*)&Wd[k][tx * 2];
        u64 b0 = __double_as_longlong(wv.x);
        u64 b1 = __double_as_longlong(wv.y);
        u64 av[8] = {
            __double_as_longlong(a0.x), __double_as_longlong(a0.y),
            __double_as_longlong(a1.x), __double_as_longlong(a1.y),
            __double_as_longlong(a2.x), __double_as_longlong(a2.y),
            __double_as_longlong(a3.x), __double_as_longlong(a3.y) };
        #pragma unroll
        for (int rp = 0; rp < 8; rp++) {
            acc[rp][0] = fma2(av[rp], b0, acc[rp][0]);
            acc[rp][1] = fma2(av[rp], b1, acc[rp][1]);
        }
    }

    int c0 = nBase + tx * 2;
    float bv0 = (c0 < N)     ? bias[c0]     : 0.0f;
    float bv1 = (c0 + 1 < N) ? bias[c0 + 1] : 0.0f;
    #pragma unroll
    for (int rp = 0; rp < 8; rp++) {
        int row0 = rowBase + ty * 16 + rp * 2;
        float x0, x1, y0, y1;
        unpack2(acc[rp][0], x0, x1);        // col c0, rows row0/row0+1
        unpack2(acc[rp][1], y0, y1);        // col c0+1
        float v00 = x0 + bv0, v01 = y0 + bv1;
        float v10 = x1 + bv0, v11 = y1 + bv1;
        if (RELU) {
            v00 = fmaxf(v00, 0.f); v01 = fmaxf(v01, 0.f);
            v10 = fmaxf(v10, 0.f); v11 = fmaxf(v11, 0.f);
        }
        if (c0 < N)     { C[row0 * N + c0] = v00;       C[(row0+1) * N + c0] = v10; }
        if (c0 + 1 < N) { C[row0 * N + c0 + 1] = v01;   C[(row0+1) * N + c0 + 1] = v11; }
    }
}

// ============================================================================
// gemm64_ln: Y = LN(Y + A @ W^T + bias), N=K=64, fused epilogue.
// ============================================================================
__global__ __launch_bounds__(128) void gemm64_ln(
    const float* __restrict__ A, const float* __restrict__ W,
    const float* __restrict__ bias, float* __restrict__ Y,
    const float* __restrict__ gam, const float* __restrict__ bet)
{
    __shared__ float As[64][64];
    __shared__ u64  Wd[64][64];
    int tid = threadIdx.x;
    int rowBase = blockIdx.x * 64;

    int sn = tid >> 1, half = tid & 1;
    {
        const float* ap = A + (rowBase + sn) * 64 + half * 32;
        const float* wp = W + sn * 64 + half * 32;
        #pragma unroll
        for (int j = 0; j < 8; j++) {
            float4 va = *(const float4*)(ap + j * 4);
            float4 vw = *(const float4*)(wp + j * 4);
            int k = half * 32 + j * 4;
            As[k][sn] = va.x; As[k+1][sn] = va.y; As[k+2][sn] = va.z; As[k+3][sn] = va.w;
            Wd[k][sn]   = pack2(vw.x, vw.x);
            Wd[k+1][sn] = pack2(vw.y, vw.y);
            Wd[k+2][sn] = pack2(vw.z, vw.z);
            Wd[k+3][sn] = pack2(vw.w, vw.w);
        }
    }
    __syncthreads();

    int tx = tid & 31, ty = tid >> 5;
    u64 acc[8][2] = {};
    #pragma unroll 16
    for (int k = 0; k < 64; k++) {
        double2 a0 = *(const double2*)&As[k][ty * 16 + 0];
        double2 a1 = *(const double2*)&As[k][ty * 16 + 4];
        double2 a2 = *(const double2*)&As[k][ty * 16 + 8];
        double2 a3 = *(const double2*)&As[k][ty * 16 + 12];
        double2 wv = *(const double2*)&Wd[k][tx * 2];
        u64 b0 = __double_as_longlong(wv.x);
        u64 b1 = __double_as_longlong(wv.y);
        u64 av[8] = {
            __double_as_longlong(a0.x), __double_as_longlong(a0.y),
            __double_as_longlong(a1.x), __double_as_longlong(a1.y),
            __double_as_longlong(a2.x), __double_as_longlong(a2.y),
            __double_as_longlong(a3.x), __double_as_longlong(a3.y) };
        #pragma unroll
        for (int rp = 0; rp < 8; rp++) {
            acc[rp][0] = fma2(av[rp], b0, acc[rp][0]);
            acc[rp][1] = fma2(av[rp], b1, acc[rp][1]);
        }
    }
    __syncthreads();   // all done reading As/Wd

    // Z = resid + acc + bias into As (reuse)
    int c0 = tx * 2;
    float bv0 = bias[c0], bv1 = bias[c0 + 1];
    #pragma unroll
    for (int rp = 0; rp < 8; rp++) {
        int row0 = ty * 16 + rp * 2;
        float x0, x1, y0, y1;
        unpack2(acc[rp][0], x0, x1);
        unpack2(acc[rp][1], y0, y1);
        float2 r0 = *(const float2*)&Y[(rowBase + row0) * 64 + c0];
        float2 r1 = *(const float2*)&Y[(rowBase + row0 + 1) * 64 + c0];
        float2 z0 = make_float2(x0 + bv0 + r0.x, y0 + bv1 + r0.y);
        float2 z1 = make_float2(x1 + bv0 + r1.x, y1 + bv1 + r1.y);
        *(float2*)&As[row0][c0]     = z0;
        *(float2*)&As[row0 + 1][c0] = z1;
    }
    __syncthreads();

    // LN: 4 warps x 16 rows
    int wid = tid >> 5, lane = tid & 31;
    #pragma unroll 1
    for (int i = 0; i < 16; i++) {
        int row = wid * 16 + i;
        float z0 = As[row][lane];
        float z1 = As[row][lane + 32];
        float s = z0 + z1;
        float ss = z0 * z0 + z1 * z1;
        #pragma unroll
        for (int off = 16; off; off >>= 1) {
            s  += __shfl_xor_sync(0xFFFFFFFFu, s, off);
            ss += __shfl_xor_sync(0xFFFFFFFFu, ss, off);
        }
        float mean = s * (1.0f / 64.0f);
        float var = ss * (1.0f / 64.0f) - mean * mean;
        float inv = rsqrtf(var + EPSV);
        Y[(rowBase + row) * 64 + lane]      = (z0 - mean) * inv * gam[lane]      + bet[lane];
        Y[(rowBase + row) * 64 + 32 + lane] = (z1 - mean) * inv * gam[32 + lane] + bet[32 + lane];
    }
}

// ============================================================================
// gemm_sk: partial[z][M,64] = A[M, kchunk] @ W[64, kchunk]^T  (no bias, no atomics)
// ============================================================================
__global__ __launch_bounds__(128) void gemm_sk(
    const float* __restrict__ A, const float* __restrict__ W,
    float* __restrict__ Cpart, int K)
{
    __shared__ float As[64][64];
    __shared__ u64  Wd[64][64];
    int tid = threadIdx.x;
    int rowBase = blockIdx.y * 64;
    int kChunk = K / gridDim.z;
    int kStart = blockIdx.z * kChunk;
    float* Cp = Cpart + blockIdx.z * (BSR * 64);

    int sn = tid >> 1, half = tid & 1;
    int tx = tid & 31, ty = tid >> 5;
    u64 acc[8][2] = {};

    for (int k0 = kStart; k0 < kStart + kChunk; k0 += 64) {
        __syncthreads();
        const float* ap = A + (rowBase + sn) * K + k0 + half * 32;
        const float* wp = W + sn * K + k0 + half * 32;
        #pragma unroll
        for (int j = 0; j < 8; j++) {
            float4 va = *(const float4*)(ap + j * 4);
            float4 vw = *(const float4*)(wp + j * 4);
            int k = half * 32 + j * 4;
            As[k][sn] = va.x; As[k+1][sn] = va.y; As[k+2][sn] = va.z; As[k+3][sn] = va.w;
            Wd[k][sn]   = pack2(vw.x, vw.x);
            Wd[k+1][sn] = pack2(vw.y, vw.y);
            Wd[k+2][sn] = pack2(vw.z, vw.z);
            Wd[k+3][sn] = pack2(vw.w, vw.w);
        }
        __syncthreads();
        #pragma unroll 16
        for (int k = 0; k < 64; k++) {
            double2 a0 = *(const double2*)&As[k][ty * 16 + 0];
            double2 a1 = *(const double2*)&As[k][ty * 16 + 4];
            double2 a2 = *(const double2*)&As[k][ty * 16 + 8];
            double2 a3 = *(const double2*)&As[k][ty * 16 + 12];
            double2 wv = *(const double2*)&Wd[k][tx * 2];
            u64 b0 = __double_as_longlong(wv.x);
            u64 b1 = __double_as_longlong(wv.y);
            u64 av[8] = {
                __double_as_longlong(a0.x), __double_as_longlong(a0.y),
                __double_as_longlong(a1.x), __double_as_longlong(a1.y),
                __double_as_longlong(a2.x), __double_as_longlong(a2.y),
                __double_as_longlong(a3.x), __double_as_longlong(a3.y) };
            #pragma unroll
            for (int rp = 0; rp < 8; rp++) {
                acc[rp][0] = fma2(av[rp], b0, acc[rp][0]);
                acc[rp][1] = fma2(av[rp], b1, acc[rp][1]);
            }
        }
    }

    int c0 = tx * 2;
    #pragma unroll
    for (int rp = 0; rp < 8; rp++) {
        int row0 = rowBase + ty * 16 + rp * 2;
        float x0, x1, y0, y1;
        unpack2(acc[rp][0], x0, x1);
        unpack2(acc[rp][1], y0, y1);
        *(float2*)&Cp[row0 * 64 + c0]       = make_float2(x0, y0);
        *(float2*)&Cp[(row0 + 1) * 64 + c0] = make_float2(x1, y1);
    }
}

// ---------------- merge split-K partials + bias + residual + LN ----------------
__global__ __launch_bounds__(256) void add_ln_ff(
    float* __restrict__ Y, const float* __restrict__ part,
    const float* __restrict__ bias,
    const float* __restrict__ gam, const float* __restrict__ bet)
{
    int row = blockIdx.x * 8 + (threadIdx.x >> 5);
    int lane = threadIdx.x & 31;
    float z0 = Y[row * 64 + lane]      + bias[lane];
    float z1 = Y[row * 64 + 32 + lane] + bias[32 + lane];
    #pragma unroll
    for (int z = 0; z < ZSPL; z++) {
        z0 += part[z * (BSR * 64) + row * 64 + lane];
        z1 += part[z * (BSR * 64) + row * 64 + 32 + lane];
    }
    float s = z0 + z1;
    float ss = z0 * z0 + z1 * z1;
    #pragma unroll
    for (int off = 16; off; off >>= 1) {
        s  += __shfl_xor_sync(0xFFFFFFFFu, s, off);
        ss += __shfl_xor_sync(0xFFFFFFFFu, ss, off);
    }
    float mean = s * (1.0f / 64.0f);
    float var = ss * (1.0f / 64.0f) - mean * mean;
    float inv = rsqrtf(var + EPSV);
    Y[row * 64 + lane]      = (z0 - mean) * inv * gam[lane]      + bet[lane];
    Y[row * 64 + 32 + lane] = (z1 - mean) * inv * gam[32 + lane] + bet[32 + lane];
}

// ============================================================================
// attention: unshifted softmax, Q=2 queries/thread, 3-way key split per block.
// grid (B*NH, S/256), block 384 (3 groups x 128 threads).
// ============================================================================
__global__ __launch_bounds__(384) void attention_kernel(
    const float* __restrict__ qkv, float* __restrict__ o)
{
    __shared__ __align__(16) float Kt[3][128][8];
    __shared__ __align__(16) float Vt[3][128][8];
    __shared__ float Ss[2][256];
    __shared__ float Accs[2][256][8];

    int tid = threadIdx.x;
    int g = tid >> 7;          // 0..2
    int t = tid & 127;
    int bh = blockIdx.x;
    int b = bh >> 3, h = bh & 7;
    int qbase = blockIdx.y * 256;
    int srow0 = b * SB + qbase + t;
    int srow1 = srow0 + 128;

    const float QS = 0.35355339059327373f * 1.4426950408889634f;
    const float* qp0 = qkv + srow0 * 192 + h * 8;
    const float* qp1 = qkv + srow1 * 192 + h * 8;
    float4 qa0 = *(const float4*)qp0, qb0 = *(const float4*)(qp0 + 4);
    float4 qa1 = *(const float4*)qp1, qb1 = *(const float4*)(qp1 + 4);
    u64 q0_01 = pack2(qa0.x * QS, qa0.y * QS), q0_23 = pack2(qa0.z * QS, qa0.w * QS);
    u64 q0_45 = pack2(qb0.x * QS, qb0.y * QS), q0_67 = pack2(qb0.z * QS, qb0.w * QS);
    u64 q1_01 = pack2(qa1.x * QS, qa1.y * QS), q1_23 = pack2(qa1.z * QS, qa1.w * QS);
    u64 q1_45 = pack2(qb1.x * QS, qb1.y * QS), q1_67 = pack2(qb1.z * QS, qb1.w * QS);

    float sum0 = 0.0f, sum1 = 0.0f;
    u64 ac0[4] = {}, ac1[4] = {};

    for (int tile = g; tile < 18; tile += 3) {
        int krow = b * SB + tile * 128 + t;
        const float* kp = qkv + krow * 192 + 64 + h * 8;
        float4 k0 = *(const float4*)kp;
        float4 k1 = *(const float4*)(kp + 4);
        float4 v0 = *(const float4*)(kp + 64);
        float4 v1 = *(const float4*)(kp + 68);
        *(float4*)&Kt[g][t][0] = k0; *(float4*)&Kt[g][t][4] = k1;
        *(float4*)&Vt[g][t][0] = v0; *(float4*)&Vt[g][t][4] = v1;
        asm volatile("bar.sync %0, 128;" :: "r"(g + 1) : "memory");

        #pragma unroll 8
        for (int kk = 0; kk < 128; kk++) {
            double2 ka = *(const double2*)&Kt[g][kk][0];
            double2 kb = *(const double2*)&Kt[g][kk][4];
            u64 kx0 = __double_as_longlong(ka.x), kx1 = __double_as_longlong(ka.y);
            u64 kx2 = __double_as_longlong(kb.x), kx3 = __double_as_longlong(kb.y);
            u64 d0 = mul2(q0_01, kx0);
            d0 = fma2(q0_23, kx1, d0);
            d0 = fma2(q0_45, kx2, d0);
            d0 = fma2(q0_67, kx3, d0);
            u64 d1 = mul2(q1_01, kx0);
            d1 = fma2(q1_23, kx1, d1);
            d1 = fma2(q1_45, kx2, d1);
            d1 = fma2(q1_67, kx3, d1);
            float l0, h0, l1, h1;
            unpack2(d0, l0, h0);
            unpack2(d1, l1, h1);
            float e0 = ex2f(l0 + h0);
            float e1 = ex2f(l1 + h1);
            sum0 += e0; sum1 += e1;
            u64 pe0 = pack2(e0, e0);
            u64 pe1 = pack2(e1, e1);
            double2 va = *(const double2*)&Vt[g][kk][0];
            double2 vb = *(const double2*)&Vt[g][kk][4];
            u64 vx0 = __double_as_longlong(va.x), vx1 = __double_as_longlong(va.y);
            u64 vx2 = __double_as_longlong(vb.x), vx3 = __double_as_longlong(vb.y);
            ac0[0] = fma2(pe0, vx0, ac0[0]); ac0[1] = fma2(pe0, vx1, ac0[1]);
            ac0[2] = fma2(pe0, vx2, ac0[2]); ac0[3] = fma2(pe0, vx3, ac0[3]);
            ac1[0] = fma2(pe1, vx0, ac1[0]); ac1[1] = fma2(pe1, vx1, ac1[1]);
            ac1[2] = fma2(pe1, vx2, ac1[2]); ac1[3] = fma2(pe1, vx3, ac1[3]);
        }
        asm volatile("bar.sync %0, 128;" :: "r"(g + 1) : "memory");
    }

    float av0[8], av1[8];
    unpack2(ac0[0], av0[0], av0[1]); unpack2(ac0[1], av0[2], av0[3]);
    unpack2(ac0[2], av0[4], av0[5]); unpack2(ac0[3], av0[6], av0[7]);
    unpack2(ac1[0], av1[0], av1[1]); unpack2(ac1[1], av1[2], av1[3]);
    unpack2(ac1[2], av1[4], av1[5]); unpack2(ac1[3], av1[6], av1[7]);

    if (g > 0) {
        Ss[g - 1][t] = sum0;
        Ss[g - 1][t + 128] = sum1;
        #pragma unroll
        for (int j = 0; j < 8; j++) {
            Accs[g - 1][t][j] = av0[j];
            Accs[g - 1][t + 128][j] = av1[j];
        }
    }
    __syncthreads();
    if (g == 0) {
        sum0 += Ss[0][t] + Ss[1][t];
        sum1 += Ss[0][t + 128] + Ss[1][t + 128];
        #pragma unroll
        for (int j = 0; j < 8; j++) {
            av0[j] += Accs[0][t][j] + Accs[1][t][j];
            av1[j] += Accs[0][t + 128][j] + Accs[1][t + 128][j];
        }
        float inv0 = 1.0f / sum0;
        float inv1 = 1.0f / sum1;
        float* op0 = o + srow0 * 64 + h * 8;
        float* op1 = o + srow1 * 64 + h * 8;
        *(float4*)op0       = make_float4(av0[0]*inv0, av0[1]*inv0, av0[2]*inv0, av0[3]*inv0);
        *(float4*)(op0 + 4) = make_float4(av0[4]*inv0, av0[5]*inv0, av0[6]*inv0, av0[7]*inv0);
        *(float4*)op1       = make_float4(av1[0]*inv1, av1[1]*inv1, av1[2]*inv1, av1[3]*inv1);
        *(float4*)(op1 + 4) = make_float4(av1[4]*inv1, av1[5]*inv1, av1[6]*inv1, av1[7]*inv1);
    }
}

// ---------------- final softmax over 441 + transpose to [B,441,S] ----------
__global__ __launch_bounds__(128) void softmax_t_kernel(
    const float* __restrict__ sc, float* __restrict__ outK)
{
    __shared__ float red[128];
    int row = blockIdx.x;
    int b = row / SB, s = row % SB;
    int tid = threadIdx.x;
    float v[4];
    float mx = -1e30f;
    #pragma unroll
    for (int i = 0; i < 4; i++) {
        int p = tid + i * 128;
        v[i] = (p < KK2) ? sc[row * KK2 + p] : -1e30f;
        mx = fmaxf(mx, v[i]);
    }
    red[tid] = mx; __syncthreads();
    for (int o = 64; o; o >>= 1) { if (tid < o) red[tid] = fmaxf(red[tid], red[tid + o]); __syncthreads(); }
    float m = red[0]; __syncthreads();
    float sum = 0.0f;
    #pragma unroll
    for (int i = 0; i < 4; i++) {
        int p = tid + i * 128;
        v[i] = (p < KK2) ? __expf(v[i] - m) : 0.0f;
        sum += v[i];
    }
    red[tid] = sum; __syncthreads();
    for (int o = 64; o; o >>= 1) { if (tid < o) red[tid] += red[tid + o]; __syncthreads(); }
    float inv = 1.0f / red[0];
    #pragma unroll
    for (int i = 0; i < 4; i++) {
        int p = tid + i * 128;
        if (p < KK2) outK[(b * KK2 + p) * SB + s] = v[i] * inv;
    }
}

// ---------------- apply predicted kernel (reflect pad) ----------------
__global__ __launch_bounds__(256) void apply_kernel(
    const float* __restrict__ x, const float* __restrict__ kern, float* __restrict__ out)
{
    int idx = blockIdx.x * 256 + threadIdx.x;
    if (idx >= BB * CC * HH * WWD) return;
    int ww = idx % WWD;
    int hh = (idx / WWD) % HH;
    int c = (idx / (HH * WWD)) % CC;
    int b = idx / (CC * HH * WWD);
    const float* kb = kern + b * KK2 * SB + hh * WWD + ww;
    const float* xb = x + (b * CC + c) * HH * WWD;
    float acc = 0.0f;
    #pragma unroll 1
    for (int kh = 0; kh < KS; kh++) {
        int ih = hh + kh - 10;
        if (ih < 0) ih = -ih;
        else if (ih >= HH) ih = 2 * HH - 2 - ih;
        const float* xr = xb + ih * WWD;
        #pragma unroll
        for (int kw = 0; kw < KS; kw++) {
            int iw = ww + kw - 10;
            if (iw < 0) iw = -iw;
            else if (iw >= WWD) iw = 2 * WWD - 2 - iw;
            acc = fmaf(xr[iw], kb[(kh * KS + kw) * SB], acc);
        }
    }
    out[idx] = acc;
}

// ---------------- host launcher ----------------
extern "C" void kernel_launch(void* const* d_in, const int* in_sizes, int n_in,
                              void* d_out, int out_size)
{
    const float* x        = (const float*)d_in[0];
    const float* conv1_w  = (const float*)d_in[1];
    const float* conv1_b  = (const float*)d_in[2];
    const float* bn_gamma = (const float*)d_in[3];
    const float* bn_beta  = (const float*)d_in[4];
    const float* bn_mean  = (const float*)d_in[5];
    const float* bn_var   = (const float*)d_in[6];
    const float* attn_in_w  = (const float*)d_in[7];
    const float* attn_in_b  = (const float*)d_in[8];
    const float* attn_out_w = (const float*)d_in[9];
    const float* attn_out_b = (const float*)d_in[10];
    const float* lin1_w   = (const float*)d_in[11];
    const float* lin1_b   = (const float*)d_in[12];
    const float* lin2_w   = (const float*)d_in[13];
    const float* lin2_b   = (const float*)d_in[14];
    const float* ln1_g    = (const float*)d_in[15];
    const float* ln1_b    = (const float*)d_in[16];
    const float* ln2_g    = (const float*)d_in[17];
    const float* ln2_b    = (const float*)d_in[18];
    const float* last_w   = (const float*)d_in[19];
    const float* last_b   = (const float*)d_in[20];

    float* out = (float*)d_out;
    float* kern = out + BB * CC * HH * WWD;

    float *py, *pqkv, *pattno, *ppart, *pff;
    cudaGetSymbolAddress((void**)&py, g_y);
    cudaGetSymbolAddress((void**)&pqkv, g_qkv);
    cudaGetSymbolAddress((void**)&pattno, g_attno);
    cudaGetSymbolAddress((void**)&ppart, g_part);
    cudaGetSymbolAddress((void**)&pff, g_ff);

    conv_bn_relu<<<(BSR * DD + 255) / 256, 256>>>(x, conv1_w, conv1_b, bn_gamma,
                                                  bn_beta, bn_mean, bn_var, py);

    for (int l = 0; l < NLAYER; l++) {
        // qkv = y @ Win^T + b   [4608,192]
        gemm64d<0><<<dim3(3, BSR / 64), 128>>>(
            py, attn_in_w + l * 192 * DD, attn_in_b + l * 192, pqkv, 192);
        // attention -> attno [4608,64]
        attention_kernel<<<dim3(BB * NHH, SB / 256), 384>>>(pqkv, pattno);
        // y = LN(y + attno @ Wout^T + b)   (fused)
        gemm64_ln<<<BSR / 64, 128>>>(
            pattno, attn_out_w + l * DD * DD, attn_out_b + l * DD, py,
            ln1_g + l * DD, ln1_b + l * DD);
        // ff1 = relu(y @ W1^T + b1)  [4608,2048]
        gemm64d<1><<<dim3(FFD / 64, BSR / 64), 128>>>(
            py, lin1_w + l * FFD * DD, lin1_b + l * FFD, pff, FFD);
        // ff2 partials: ff1 @ W2^T  [ZSPL][4608,64]
        gemm_sk<<<dim3(1, BSR / 64, ZSPL), 128>>>(pff, lin2_w + l * DD * FFD, ppart, FFD);
        // y = LN(y + sum(partials) + b2)
        add_ln_ff<<<BSR / 8, 256>>>(py, ppart, lin2_b + l * DD,
                                    ln2_g + l * DD, ln2_b + l * DD);
    }

    // scores = y @ last_w^T + last_b  [4608,441]
    gemm64d<0><<<dim3((KK2 + 63) / 64, BSR / 64), 128>>>(py, last_w, last_b, pff, KK2);
    softmax_t_kernel<<<BSR, 128>>>(pff, kern);
    apply_kernel<<<(BB * CC * HH * WWD + 255) / 256, 256>>>(x, kern, out);
}